// round 5
// baseline (speedup 1.0000x reference)
#include <cuda_runtime.h>
#include <cuda_fp16.h>
#include <cstdint>

// ---------------------------------------------------------------- constants
#define B_   8
#define CG   192
#define OG   192
#define HP   66
#define WP   322
#define HC   64
#define WC   320
#define KTOT 1344            // CG * 7 hex taps
#define NCH  42              // KTOT / 32
#define NTHR 256

// Weights (half) in mma-fragment layout:
// [chunk42][ks2][nb24][lane32][4 halves] (reg*2+half)
__device__ __half g_Kt[NCH * 6144];

// tap -> offset (dy*WP + dx) for hex positions
__constant__ int c_off[7] = {WP + 1, 0, 1, WP + 2, 2 * WP + 2, 2 * WP + 1, WP};

// ---------------------------------------------------------------- utils
__device__ __forceinline__ uint32_t smem_u32(const void* p) {
    uint32_t a;
    asm("{ .reg .u64 t; cvta.to.shared.u64 t, %1; cvt.u32.u64 %0, t; }"
        : "=r"(a) : "l"(p));
    return a;
}

// ---------------------------------------------------------------- prep
__global__ void prep_kernel(const float* __restrict__ w) {
    int tid = blockIdx.x * blockDim.x + threadIdx.x;
    if (tid >= OG * CG) return;
    int og = tid / CG;
    int cg = tid % CG;
    int o = og / 12, g = og % 12;
    int c = cg / 12, h = cg % 12;
    int fg = g / 6, rg = g % 6;
    int fh = h / 6, rh = h % 6;
    int f = fg ^ fh;
    int r = (fg == 0) ? ((rh - rg + 6) % 6) : ((rg - rh + 6) % 6);
    int p = f * 6 + r;
    const float* wp = w + ((o * 16 + c) * 12 + p) * 7;

    float vals[7];
    vals[0] = wp[0];
#pragma unroll
    for (int i = 0; i < 6; i++) {
        int src = (fg == 0) ? ((i - rg + 12) % 6) : ((rg - i + 12) % 6);
        vals[1 + i] = wp[1 + src];
    }

    int nb = og >> 3;
    int n  = og & 7;
#pragma unroll
    for (int t = 0; t < 7; t++) {
        int k    = cg * 7 + t;
        int ch   = k >> 5;
        int kk   = k & 31;
        int ks   = kk >> 4;
        int kk16 = kk & 15;
        int lane = n * 4 + ((kk16 & 7) >> 1);
        int reg  = kk16 >> 3;
        int half = kk16 & 1;
        g_Kt[(size_t)(((ch * 2 + ks) * 24 + nb) * 32 + lane) * 4 + reg * 2 + half] =
            __float2half_rn(vals[t]);
    }
}

// ---------------------------------------------------------------- conv
// SMEM: A 2 stages x 8KB at 0 ; B 2 stages x 6KB at 16384 ; bias at 28672
#define SMEM_B_OFF 16384
#define SMEM_BIAS  28672
#define SMEM_TOT   (28672 + 512)

__global__ void __launch_bounds__(NTHR, 2) conv_mma(
    const float* __restrict__ x,
    const float* __restrict__ bias,
    float* __restrict__ out)
{
    extern __shared__ char smem[];
    const uint32_t sb = smem_u32(smem);
    const int tid  = threadIdx.x;
    const int lane = tid & 31;
    const int wrp  = tid >> 5;
    const int wm   = wrp >> 2;      // 0..1 (consumer M)
    const int wn   = wrp & 3;       // 0..3 (consumer N)
    const int bz   = blockIdx.z;
    const int b    = bz >> 1;
    const int oh   = bz & 1;        // og half: 96 channels
    const int cy0  = blockIdx.y * 2;
    const int cx0  = blockIdx.x * 64;

    if (tid < 96) ((float*)(smem + SMEM_BIAS))[tid] = bias[(oh * 96 + tid) / 12];

    // ---- A producer constants (conflict-free mapping) ----
    // kpair_local = (lane&7) + (wrp>>2)*8 ; ks = wrp>>2
    // mr = ((lane>>3)&1) | ((wrp&3)<<1) | ((lane>>4)<<3)
    const int kpl = (lane & 7) + (wrp >> 2) * 8;       // 0..15
    const int p_ks = wrp >> 2;
    const int mr  = ((lane >> 3) & 1) | ((wrp & 3) << 1) | ((lane >> 4) << 3);
    const int kb   = kpl & 3;
    const int kreg = (kpl >> 2) & 1;
    const int lane16 = (mr & 7) * 4 + kb;
    const int sreg   = (mr >> 3) + kreg * 2;
    const uint32_t a_sts0 = sb + (uint32_t)(p_ks * 4096 + lane16 * 16 + sreg * 4);

    const size_t plane = (size_t)HP * WP;
    // pixel column offset mr folded into base; iter adds (e>>2)*WP + (e&3)*16
    const float* xb = x + (size_t)b * CG * plane + (size_t)cy0 * WP + cx0 + mr;

    uint32_t v[8];

    float acc[4][3][4];
#pragma unroll
    for (int i = 0; i < 4; i++)
#pragma unroll
        for (int j = 0; j < 3; j++)
#pragma unroll
            for (int q = 0; q < 4; q++) acc[i][j][q] = 0.f;

#define LOAD_A_CHUNK(ch)                                                      \
    do {                                                                      \
        int k0 = (ch) * 32 + kpl * 2;                                         \
        int k1 = k0 + 1;                                                      \
        const float* p0 = xb + (size_t)(k0 / 7) * plane + c_off[k0 % 7];      \
        const float* p1 = xb + (size_t)(k1 / 7) * plane + c_off[k1 % 7];      \
        _Pragma("unroll")                                                     \
        for (int e = 0; e < 8; e++) {                                         \
            int off = (e >> 2) * WP + (e & 3) * 16;                           \
            float f0 = __ldg(p0 + off);                                       \
            float f1 = __ldg(p1 + off);                                       \
            __half2 hh = __halves2half2(__float2half_rn(f0), __float2half_rn(f1)); \
            v[e] = *(uint32_t*)&hh;                                           \
        }                                                                     \
    } while (0)

#define STORE_A_CHUNK(stage)                                                  \
    do {                                                                      \
        uint32_t base = a_sts0 + (stage) * 8192;                              \
        _Pragma("unroll")                                                     \
        for (int e = 0; e < 8; e++)                                           \
            asm volatile("st.shared.b32 [%0], %1;"                            \
                         :: "r"(base + e * 512), "r"(v[e]));                  \
    } while (0)

    // B chunk for this og-half: per ks, 12 nb-blocks x 256B = 3KB (contiguous)
#define LOAD_B_CHUNK(ch, stage)                                               \
    do {                                                                      \
        _Pragma("unroll")                                                     \
        for (int i = 0; i < 2; i++) {                                         \
            int u = tid + i * NTHR;                                           \
            if (u < 384) {                                                    \
                int bks = (u >= 192);                                         \
                int off = u - bks * 192;                                      \
                const __half* src = g_Kt                                      \
                    + (size_t)(((ch) * 2 + bks) * 24 + oh * 12) * 128         \
                    + off * 8;                                                \
                uint32_t dst = sb + SMEM_B_OFF + (stage) * 6144               \
                             + bks * 3072 + off * 16;                         \
                asm volatile("cp.async.cg.shared.global [%0], [%1], 16;"      \
                             :: "r"(dst), "l"(src) : "memory");               \
            }                                                                 \
        }                                                                     \
        asm volatile("cp.async.commit_group;" ::: "memory");                  \
    } while (0)

    // ---- stage 0 fill ----
    LOAD_A_CHUNK(0);
    LOAD_B_CHUNK(0, 0);
    STORE_A_CHUNK(0);
    asm volatile("cp.async.wait_group 0;" ::: "memory");
    __syncthreads();

    // ---- main K loop ----
    for (int ch = 0; ch < NCH; ch++) {
        const int s = ch & 1;
        if (ch + 1 < NCH) {
            LOAD_A_CHUNK(ch + 1);
            LOAD_B_CHUNK(ch + 1, s ^ 1);
        }

        const uint32_t Ab = sb + s * 8192 + (uint32_t)((wm * 4) * 512 + lane * 16);
        const uint32_t Bb = sb + SMEM_B_OFF + s * 6144
                          + (uint32_t)((wn * 3) * 256 + lane * 8);
#pragma unroll
        for (int ks = 0; ks < 2; ks++) {
            uint32_t a[4][4];
#pragma unroll
            for (int mf = 0; mf < 4; mf++)
                asm volatile("ld.shared.v4.b32 {%0,%1,%2,%3}, [%4];"
                    : "=r"(a[mf][0]), "=r"(a[mf][1]), "=r"(a[mf][2]), "=r"(a[mf][3])
                    : "r"(Ab + ks * 4096 + mf * 512));
            uint32_t bf[3][2];
#pragma unroll
            for (int nf = 0; nf < 3; nf++)
                asm volatile("ld.shared.v2.b32 {%0,%1}, [%2];"
                    : "=r"(bf[nf][0]), "=r"(bf[nf][1])
                    : "r"(Bb + ks * 3072 + nf * 256));
#pragma unroll
            for (int mf = 0; mf < 4; mf++)
#pragma unroll
                for (int nf = 0; nf < 3; nf++)
                    asm volatile(
                        "mma.sync.aligned.m16n8k16.row.col.f32.f16.f16.f32 "
                        "{%0,%1,%2,%3}, {%4,%5,%6,%7}, {%8,%9}, {%0,%1,%2,%3};"
                        : "+f"(acc[mf][nf][0]), "+f"(acc[mf][nf][1]),
                          "+f"(acc[mf][nf][2]), "+f"(acc[mf][nf][3])
                        : "r"(a[mf][0]), "r"(a[mf][1]), "r"(a[mf][2]), "r"(a[mf][3]),
                          "r"(bf[nf][0]), "r"(bf[nf][1]));
        }

        if (ch + 1 < NCH) STORE_A_CHUNK(s ^ 1);
        asm volatile("cp.async.wait_group 0;" ::: "memory");
        __syncthreads();
    }

    // ---- epilogue: bias + store interior ----
    const float* bs = (const float*)(smem + SMEM_BIAS);
#pragma unroll
    for (int mf = 0; mf < 4; mf++) {
#pragma unroll
        for (int half = 0; half < 2; half++) {
            int m  = wm * 64 + mf * 16 + (lane >> 2) + half * 8;
            int ry = m >> 6, rx = m & 63;
            float* orow = out + ((size_t)b * OG * HP + (size_t)(cy0 + ry + 1)) * WP
                        + (size_t)(oh * 96) * plane + (cx0 + rx + 1);
#pragma unroll
            for (int nf = 0; nf < 3; nf++) {
                int og = wn * 24 + nf * 8 + (lane & 3) * 2;
                orow[(size_t)og * plane]       = acc[mf][nf][half * 2 + 0] + bs[og];
                orow[(size_t)(og + 1) * plane] = acc[mf][nf][half * 2 + 1] + bs[og + 1];
            }
        }
    }
}

// ---------------------------------------------------------------- boundary
__global__ void boundary_kernel(float* __restrict__ out) {
    const int PER = 2 * WP + 2 * HC;   // 772
    int tid = blockIdx.x * blockDim.x + threadIdx.x;
    int total = B_ * OG * PER;
    if (tid >= total) return;

    int p   = tid % PER;
    int bog = tid / PER;
    int og  = bog % OG;
    int b   = bog / OG;

    int y, xx;
    if (p < WP)               { y = 0;      xx = p; }
    else if (p < 2 * WP)      { y = HP - 1; xx = p - WP; }
    else if (p < 2 * WP + HC) { xx = 0;      y = p - 2 * WP + 1; }
    else                      { xx = WP - 1; y = p - (2 * WP + HC) + 1; }

    int sx = xx, dt = 0;
    if (xx == 0)           { sx = WP - 2; dt = 1; }
    else if (xx == WP - 1) { sx = 1;      dt = -1; }
    int sy = y;
    if (y == 0)            sy = HP - 2;
    else if (y == HP - 1)  sy = 1;

    int o = og / 12, t = og % 12;
    int f = t / 6,   rr = t % 6;
    int gp = f * 6 + ((rr + dt + 6) % 6);
    int og_src = o * 12 + gp;

    out[((size_t)(b * OG + og) * HP + y) * WP + xx] =
        out[((size_t)(b * OG + og_src) * HP + sy) * WP + sx];
}

// ---------------------------------------------------------------- launch
extern "C" void kernel_launch(void* const* d_in, const int* in_sizes, int n_in,
                              void* d_out, int out_size) {
    (void)in_sizes; (void)n_in; (void)out_size;
    const float* x    = (const float*)d_in[0];
    const float* w    = (const float*)d_in[1];
    const float* bias = (const float*)d_in[2];
    float* out = (float*)d_out;

    prep_kernel<<<(OG * CG + 255) / 256, 256>>>(w);

    dim3 grid(WC / 64, HC / 2, B_ * 2);   // (5, 32, 16) = 2560 CTAs
    conv_mma<<<grid, NTHR, SMEM_TOT>>>(x, bias, out);

    int total = B_ * OG * (2 * WP + 2 * HC);
    boundary_kernel<<<(total + 255) / 256, 256>>>(out);
}

// round 6
// speedup vs baseline: 1.4409x; 1.4409x over previous
#include <cuda_runtime.h>
#include <cuda_fp16.h>
#include <cstdint>

// ---------------------------------------------------------------- constants
#define B_   8
#define CG   192
#define OG   192
#define HP   66
#define WP   322
#define HC   64
#define WC   320
#define KTOT 1344            // CG * 7 hex taps
#define NCH  42              // KTOT / 32
#define NTHR 256

// Weights (half) in mma-fragment layout:
// [chunk42][ks2][nb24][lane32][4 halves] (reg*2+half)
__device__ __half g_Kt[NCH * 6144];

// tap -> offset (dy*WP + dx) for hex positions
__constant__ int c_off[7] = {WP + 1, 0, 1, WP + 2, 2 * WP + 2, 2 * WP + 1, WP};

// ---------------------------------------------------------------- utils
__device__ __forceinline__ uint32_t smem_u32(const void* p) {
    uint32_t a;
    asm("{ .reg .u64 t; cvta.to.shared.u64 t, %1; cvt.u32.u64 %0, t; }"
        : "=r"(a) : "l"(p));
    return a;
}

// ---------------------------------------------------------------- prep
__global__ void prep_kernel(const float* __restrict__ w) {
    int tid = blockIdx.x * blockDim.x + threadIdx.x;
    if (tid >= OG * CG) return;
    int og = tid / CG;
    int cg = tid % CG;
    int o = og / 12, g = og % 12;
    int c = cg / 12, h = cg % 12;
    int fg = g / 6, rg = g % 6;
    int fh = h / 6, rh = h % 6;
    int f = fg ^ fh;
    int r = (fg == 0) ? ((rh - rg + 6) % 6) : ((rg - rh + 6) % 6);
    int p = f * 6 + r;
    const float* wp = w + ((o * 16 + c) * 12 + p) * 7;

    float vals[7];
    vals[0] = wp[0];
#pragma unroll
    for (int i = 0; i < 6; i++) {
        int src = (fg == 0) ? ((i - rg + 12) % 6) : ((rg - i + 12) % 6);
        vals[1 + i] = wp[1 + src];
    }

    int nb = og >> 3;
    int n  = og & 7;
#pragma unroll
    for (int t = 0; t < 7; t++) {
        int k    = cg * 7 + t;
        int ch   = k >> 5;
        int kk   = k & 31;
        int ks   = kk >> 4;
        int kk16 = kk & 15;
        int lane = n * 4 + ((kk16 & 7) >> 1);
        int reg  = kk16 >> 3;
        int half = kk16 & 1;
        g_Kt[(size_t)(((ch * 2 + ks) * 24 + nb) * 32 + lane) * 4 + reg * 2 + half] =
            __float2half_rn(vals[t]);
    }
}

// ---------------------------------------------------------------- conv
// CTA = 64 px (1 row x 64 cols) x 192 og. 8 warps: 2M x 4N, warp tile 32x48.
// SMEM: A 2 stages x 4KB at 0 ; B 2 stages x 12KB at 8192 ; bias at 32768
#define SMEM_B_OFF 8192
#define SMEM_BIAS  32768
#define SMEM_TOT   (32768 + 768)

__global__ void __launch_bounds__(NTHR, 2) conv_mma(
    const float* __restrict__ x,
    const float* __restrict__ bias,
    float* __restrict__ out)
{
    extern __shared__ char smem[];
    const uint32_t sb = smem_u32(smem);
    const int tid  = threadIdx.x;
    const int lane = tid & 31;
    const int wrp  = tid >> 5;
    const int wm   = wrp >> 2;      // 0..1
    const int wn   = wrp & 3;       // 0..3
    const int b    = blockIdx.z;
    const int cy   = blockIdx.y;    // conv row 0..63
    const int cx0  = blockIdx.x * 64;

    if (tid < OG) ((float*)(smem + SMEM_BIAS))[tid] = bias[tid / 12];

    // ---- A producer constants ----
    // kpl = (lane>>4) + wrp*2  (0..15) ; m = (lane&15) + e*16 (e = mb = 0..3)
    const int kpl  = (lane >> 4) + wrp * 2;
    const int p_ks = kpl >> 3;
    const int l_c  = (kpl & 3) + (lane & 7) * 4;
    const int sreg = ((lane >> 3) & 1) + ((kpl >> 2) & 1) * 2;
    const uint32_t a_sts0 = sb + (uint32_t)(p_ks * 2048 + l_c * 16 + sreg * 4);

    const size_t plane = (size_t)HP * WP;
    const float* xb = x + (size_t)b * CG * plane + (size_t)cy * WP + cx0 + (lane & 15);

    uint32_t v[4];

    float acc[2][6][4];
#pragma unroll
    for (int i = 0; i < 2; i++)
#pragma unroll
        for (int j = 0; j < 6; j++)
#pragma unroll
            for (int q = 0; q < 4; q++) acc[i][j][q] = 0.f;

#define LOAD_A_CHUNK(ch)                                                      \
    do {                                                                      \
        int k0 = (ch) * 32 + kpl * 2;                                         \
        int k1 = k0 + 1;                                                      \
        const float* p0 = xb + (size_t)(k0 / 7) * plane + c_off[k0 % 7];      \
        const float* p1 = xb + (size_t)(k1 / 7) * plane + c_off[k1 % 7];      \
        _Pragma("unroll")                                                     \
        for (int e = 0; e < 4; e++) {                                         \
            float f0 = __ldg(p0 + e * 16);                                    \
            float f1 = __ldg(p1 + e * 16);                                    \
            __half2 hh = __halves2half2(__float2half_rn(f0), __float2half_rn(f1)); \
            v[e] = *(uint32_t*)&hh;                                           \
        }                                                                     \
    } while (0)

#define STORE_A_CHUNK(stage)                                                  \
    do {                                                                      \
        uint32_t base = a_sts0 + (stage) * 4096;                              \
        _Pragma("unroll")                                                     \
        for (int e = 0; e < 4; e++)                                           \
            asm volatile("st.shared.b32 [%0], %1;"                            \
                         :: "r"(base + e * 512), "r"(v[e]));                  \
    } while (0)

#define LOAD_B_CHUNK(ch, stage)                                               \
    do {                                                                      \
        const __half* src = g_Kt + (size_t)(ch) * 6144 + tid * 8;             \
        uint32_t dst = sb + SMEM_B_OFF + (stage) * 12288 + tid * 16;          \
        _Pragma("unroll")                                                     \
        for (int i = 0; i < 3; i++)                                           \
            asm volatile("cp.async.cg.shared.global [%0], [%1], 16;"          \
                         :: "r"(dst + i * 4096), "l"(src + i * 2048) : "memory"); \
        asm volatile("cp.async.commit_group;" ::: "memory");                  \
    } while (0)

    // ---- stage 0 fill ----
    LOAD_A_CHUNK(0);
    LOAD_B_CHUNK(0, 0);
    STORE_A_CHUNK(0);
    asm volatile("cp.async.wait_group 0;" ::: "memory");
    __syncthreads();

    // ---- main K loop ----
    for (int ch = 0; ch < NCH; ch++) {
        const int s = ch & 1;
        if (ch + 1 < NCH) {
            LOAD_A_CHUNK(ch + 1);
            LOAD_B_CHUNK(ch + 1, s ^ 1);
        }

        const uint32_t Ab = sb + s * 4096 + (uint32_t)(wm * 2 * 512 + lane * 16);
        const uint32_t Bb = sb + SMEM_B_OFF + s * 12288
                          + (uint32_t)((wn * 6) * 256 + lane * 8);
#pragma unroll
        for (int ks = 0; ks < 2; ks++) {
            uint32_t a[2][4];
#pragma unroll
            for (int mf = 0; mf < 2; mf++)
                asm volatile("ld.shared.v4.b32 {%0,%1,%2,%3}, [%4];"
                    : "=r"(a[mf][0]), "=r"(a[mf][1]), "=r"(a[mf][2]), "=r"(a[mf][3])
                    : "r"(Ab + ks * 2048 + mf * 512));
            uint32_t bf[6][2];
#pragma unroll
            for (int nf = 0; nf < 6; nf++)
                asm volatile("ld.shared.v2.b32 {%0,%1}, [%2];"
                    : "=r"(bf[nf][0]), "=r"(bf[nf][1])
                    : "r"(Bb + ks * 6144 + nf * 256));
#pragma unroll
            for (int mf = 0; mf < 2; mf++)
#pragma unroll
                for (int nf = 0; nf < 6; nf++)
                    asm volatile(
                        "mma.sync.aligned.m16n8k16.row.col.f32.f16.f16.f32 "
                        "{%0,%1,%2,%3}, {%4,%5,%6,%7}, {%8,%9}, {%0,%1,%2,%3};"
                        : "+f"(acc[mf][nf][0]), "+f"(acc[mf][nf][1]),
                          "+f"(acc[mf][nf][2]), "+f"(acc[mf][nf][3])
                        : "r"(a[mf][0]), "r"(a[mf][1]), "r"(a[mf][2]), "r"(a[mf][3]),
                          "r"(bf[nf][0]), "r"(bf[nf][1]));
        }

        if (ch + 1 < NCH) STORE_A_CHUNK(s ^ 1);
        asm volatile("cp.async.wait_group 0;" ::: "memory");
        __syncthreads();
    }

    // ---- epilogue: bias + store interior (row cy+1) ----
    const float* bs = (const float*)(smem + SMEM_BIAS);
#pragma unroll
    for (int mf = 0; mf < 2; mf++) {
#pragma unroll
        for (int half = 0; half < 2; half++) {
            int m = wm * 32 + mf * 16 + (lane >> 2) + half * 8;   // col 0..63
            float* orow = out + (size_t)b * OG * plane
                        + (size_t)(cy + 1) * WP + (cx0 + m + 1);
#pragma unroll
            for (int nf = 0; nf < 6; nf++) {
                int og = wn * 48 + nf * 8 + (lane & 3) * 2;
                orow[(size_t)og * plane]       = acc[mf][nf][half * 2 + 0] + bs[og];
                orow[(size_t)(og + 1) * plane] = acc[mf][nf][half * 2 + 1] + bs[og + 1];
            }
        }
    }
}

// ---------------------------------------------------------------- boundary
__global__ void boundary_kernel(float* __restrict__ out) {
    const int PER = 2 * WP + 2 * HC;   // 772
    int tid = blockIdx.x * blockDim.x + threadIdx.x;
    int total = B_ * OG * PER;
    if (tid >= total) return;

    int p   = tid % PER;
    int bog = tid / PER;
    int og  = bog % OG;
    int b   = bog / OG;

    int y, xx;
    if (p < WP)               { y = 0;      xx = p; }
    else if (p < 2 * WP)      { y = HP - 1; xx = p - WP; }
    else if (p < 2 * WP + HC) { xx = 0;      y = p - 2 * WP + 1; }
    else                      { xx = WP - 1; y = p - (2 * WP + HC) + 1; }

    int sx = xx, dt = 0;
    if (xx == 0)           { sx = WP - 2; dt = 1; }
    else if (xx == WP - 1) { sx = 1;      dt = -1; }
    int sy = y;
    if (y == 0)            sy = HP - 2;
    else if (y == HP - 1)  sy = 1;

    int o = og / 12, t = og % 12;
    int f = t / 6,   rr = t % 6;
    int gp = f * 6 + ((rr + dt + 6) % 6);
    int og_src = o * 12 + gp;

    out[((size_t)(b * OG + og) * HP + y) * WP + xx] =
        out[((size_t)(b * OG + og_src) * HP + sy) * WP + sx];
}

// ---------------------------------------------------------------- launch
extern "C" void kernel_launch(void* const* d_in, const int* in_sizes, int n_in,
                              void* d_out, int out_size) {
    (void)in_sizes; (void)n_in; (void)out_size;
    const float* x    = (const float*)d_in[0];
    const float* w    = (const float*)d_in[1];
    const float* bias = (const float*)d_in[2];
    float* out = (float*)d_out;

    prep_kernel<<<(OG * CG + 255) / 256, 256>>>(w);

    dim3 grid(WC / 64, HC, B_);   // (5, 64, 8) = 2560 CTAs
    conv_mma<<<grid, NTHR, SMEM_TOT>>>(x, bias, out);

    int total = B_ * OG * (2 * WP + 2 * HC);
    boundary_kernel<<<(total + 255) / 256, 256>>>(out);
}

// round 7
// speedup vs baseline: 1.7178x; 1.1922x over previous
#include <cuda_runtime.h>
#include <cuda_fp16.h>
#include <cstdint>

// ---------------------------------------------------------------- constants
#define B_   8
#define CG   192
#define OG   192
#define HP   66
#define WP   322
#define HC   64
#define WC   320
#define KTOT 1344            // CG * 7 hex taps
#define NCH  21              // KTOT / 64  (Kc = 64)
#define NTHR 256

// Weights (half) in mma-fragment layout:
// [chunk32x42][ks2][nb24][lane32][4 halves] (reg*2+half)  -- same as R6
__device__ __half g_Kt[42 * 6144];

// tap -> offset (dy*WP + dx) for hex positions
__constant__ int c_off[7] = {WP + 1, 0, 1, WP + 2, 2 * WP + 2, 2 * WP + 1, WP};

// ---------------------------------------------------------------- utils
__device__ __forceinline__ uint32_t smem_u32(const void* p) {
    uint32_t a;
    asm("{ .reg .u64 t; cvta.to.shared.u64 t, %1; cvt.u32.u64 %0, t; }"
        : "=r"(a) : "l"(p));
    return a;
}

// ---------------------------------------------------------------- prep
__global__ void prep_kernel(const float* __restrict__ w) {
    int tid = blockIdx.x * blockDim.x + threadIdx.x;
    if (tid >= OG * CG) return;
    int og = tid / CG;
    int cg = tid % CG;
    int o = og / 12, g = og % 12;
    int c = cg / 12, h = cg % 12;
    int fg = g / 6, rg = g % 6;
    int fh = h / 6, rh = h % 6;
    int f = fg ^ fh;
    int r = (fg == 0) ? ((rh - rg + 6) % 6) : ((rg - rh + 6) % 6);
    int p = f * 6 + r;
    const float* wp = w + ((o * 16 + c) * 12 + p) * 7;

    float vals[7];
    vals[0] = wp[0];
#pragma unroll
    for (int i = 0; i < 6; i++) {
        int src = (fg == 0) ? ((i - rg + 12) % 6) : ((rg - i + 12) % 6);
        vals[1 + i] = wp[1 + src];
    }

    int nb = og >> 3;
    int n  = og & 7;
#pragma unroll
    for (int t = 0; t < 7; t++) {
        int k    = cg * 7 + t;
        int ch   = k >> 5;
        int kk   = k & 31;
        int ks   = kk >> 4;
        int kk16 = kk & 15;
        int lane = n * 4 + ((kk16 & 7) >> 1);
        int reg  = kk16 >> 3;
        int half = kk16 & 1;
        g_Kt[(size_t)(((ch * 2 + ks) * 24 + nb) * 32 + lane) * 4 + reg * 2 + half] =
            __float2half_rn(vals[t]);
    }
}

// ---------------------------------------------------------------- conv
// CTA = 64 px (1 row x 64 cols) x 192 og. 8 warps: 2M x 4N, warp tile 32x48.
// Kc = 64 per iteration (two 32-K sub-blocks), 21 iterations.
// SMEM: A 2 stages x 8KB at 0 ; B 2 stages x 24KB at 16384 ; bias at 65536
#define SMEM_B_OFF 16384
#define SMEM_BIAS  65536
#define SMEM_TOT   (65536 + 768)

__global__ void __launch_bounds__(NTHR, 2) conv_mma(
    const float* __restrict__ x,
    const float* __restrict__ bias,
    float* __restrict__ out)
{
    extern __shared__ char smem[];
    const uint32_t sb = smem_u32(smem);
    const int tid  = threadIdx.x;
    const int lane = tid & 31;
    const int wrp  = tid >> 5;
    const int wm   = wrp >> 2;      // 0..1
    const int wn   = wrp & 3;       // 0..3
    const int b    = blockIdx.z;
    const int cy   = blockIdx.y;    // conv row 0..63
    const int cx0  = blockIdx.x * 64;

    if (tid < OG) ((float*)(smem + SMEM_BIAS))[tid] = bias[tid / 12];

    // ---- A producer constants (same per-32K map as R6) ----
    const int kpl  = (lane >> 4) + wrp * 2;     // 0..15 within a 32-K sub
    const int p_ks = kpl >> 3;
    const int l_c  = (kpl & 3) + (lane & 7) * 4;
    const int sreg = ((lane >> 3) & 1) + ((kpl >> 2) & 1) * 2;
    const uint32_t a_sts0 = sb + (uint32_t)(p_ks * 2048 + l_c * 16 + sreg * 4);

    const size_t plane = (size_t)HP * WP;
    const float* xb = x + (size_t)b * CG * plane + (size_t)cy * WP + cx0 + (lane & 15);

    uint32_t v[2][4];

    float acc[2][6][4];
#pragma unroll
    for (int i = 0; i < 2; i++)
#pragma unroll
        for (int j = 0; j < 6; j++)
#pragma unroll
            for (int q = 0; q < 4; q++) acc[i][j][q] = 0.f;

    // ch is a 64-K chunk index (0..20); sub u in {0,1} selects 32-K half
#define LOAD_A_CHUNK(ch)                                                      \
    do {                                                                      \
        _Pragma("unroll")                                                     \
        for (int u = 0; u < 2; u++) {                                         \
            int k0 = (ch) * 64 + u * 32 + kpl * 2;                            \
            int k1 = k0 + 1;                                                  \
            const float* p0 = xb + (size_t)(k0 / 7) * plane + c_off[k0 % 7];  \
            const float* p1 = xb + (size_t)(k1 / 7) * plane + c_off[k1 % 7];  \
            _Pragma("unroll")                                                 \
            for (int e = 0; e < 4; e++) {                                     \
                float f0 = __ldg(p0 + e * 16);                                \
                float f1 = __ldg(p1 + e * 16);                                \
                __half2 hh = __halves2half2(__float2half_rn(f0),              \
                                            __float2half_rn(f1));             \
                v[u][e] = *(uint32_t*)&hh;                                    \
            }                                                                 \
        }                                                                     \
    } while (0)

#define STORE_A_CHUNK(stage)                                                  \
    do {                                                                      \
        uint32_t base = a_sts0 + (stage) * 8192;                              \
        _Pragma("unroll")                                                     \
        for (int u = 0; u < 2; u++)                                           \
            _Pragma("unroll")                                                 \
            for (int e = 0; e < 4; e++)                                       \
                asm volatile("st.shared.b32 [%0], %1;"                        \
                             :: "r"(base + u * 4096 + e * 512), "r"(v[u][e]));\
    } while (0)

    // B 64-K chunk: 24KB linear copy (12288 halves), 6 x 16B per thread
#define LOAD_B_CHUNK(ch, stage)                                               \
    do {                                                                      \
        const __half* src = g_Kt + (size_t)(ch) * 12288 + tid * 8;            \
        uint32_t dst = sb + SMEM_B_OFF + (stage) * 24576 + tid * 16;          \
        _Pragma("unroll")                                                     \
        for (int i = 0; i < 6; i++)                                           \
            asm volatile("cp.async.cg.shared.global [%0], [%1], 16;"          \
                         :: "r"(dst + i * 4096), "l"(src + i * 2048) : "memory"); \
        asm volatile("cp.async.commit_group;" ::: "memory");                  \
    } while (0)

    // ---- stage 0 fill ----
    LOAD_A_CHUNK(0);
    LOAD_B_CHUNK(0, 0);
    STORE_A_CHUNK(0);
    asm volatile("cp.async.wait_group 0;" ::: "memory");
    __syncthreads();

    // ---- main K loop (21 chunks of 64) ----
    for (int ch = 0; ch < NCH; ch++) {
        const int s = ch & 1;
        if (ch + 1 < NCH) {
            LOAD_A_CHUNK(ch + 1);
            LOAD_B_CHUNK(ch + 1, s ^ 1);
        }

        const uint32_t Ab = sb + s * 8192 + (uint32_t)(wm * 2 * 512 + lane * 16);
        const uint32_t Bb = sb + SMEM_B_OFF + s * 24576
                          + (uint32_t)((wn * 6) * 256 + lane * 8);
#pragma unroll
        for (int ks = 0; ks < 4; ks++) {
            uint32_t a[2][4];
#pragma unroll
            for (int mf = 0; mf < 2; mf++)
                asm volatile("ld.shared.v4.b32 {%0,%1,%2,%3}, [%4];"
                    : "=r"(a[mf][0]), "=r"(a[mf][1]), "=r"(a[mf][2]), "=r"(a[mf][3])
                    : "r"(Ab + ks * 2048 + mf * 512));
            uint32_t bf[6][2];
#pragma unroll
            for (int nf = 0; nf < 6; nf++)
                asm volatile("ld.shared.v2.b32 {%0,%1}, [%2];"
                    : "=r"(bf[nf][0]), "=r"(bf[nf][1])
                    : "r"(Bb + ks * 6144 + nf * 256));
#pragma unroll
            for (int mf = 0; mf < 2; mf++)
#pragma unroll
                for (int nf = 0; nf < 6; nf++)
                    asm volatile(
                        "mma.sync.aligned.m16n8k16.row.col.f32.f16.f16.f32 "
                        "{%0,%1,%2,%3}, {%4,%5,%6,%7}, {%8,%9}, {%0,%1,%2,%3};"
                        : "+f"(acc[mf][nf][0]), "+f"(acc[mf][nf][1]),
                          "+f"(acc[mf][nf][2]), "+f"(acc[mf][nf][3])
                        : "r"(a[mf][0]), "r"(a[mf][1]), "r"(a[mf][2]), "r"(a[mf][3]),
                          "r"(bf[nf][0]), "r"(bf[nf][1]));
        }

        if (ch + 1 < NCH) STORE_A_CHUNK(s ^ 1);
        asm volatile("cp.async.wait_group 0;" ::: "memory");
        __syncthreads();
    }

    // ---- epilogue: bias + store interior (row cy+1) ----
    const float* bs = (const float*)(smem + SMEM_BIAS);
#pragma unroll
    for (int mf = 0; mf < 2; mf++) {
#pragma unroll
        for (int half = 0; half < 2; half++) {
            int m = wm * 32 + mf * 16 + (lane >> 2) + half * 8;   // col 0..63
            float* orow = out + (size_t)b * OG * plane
                        + (size_t)(cy + 1) * WP + (cx0 + m + 1);
#pragma unroll
            for (int nf = 0; nf < 6; nf++) {
                int og = wn * 48 + nf * 8 + (lane & 3) * 2;
                orow[(size_t)og * plane]       = acc[mf][nf][half * 2 + 0] + bs[og];
                orow[(size_t)(og + 1) * plane] = acc[mf][nf][half * 2 + 1] + bs[og + 1];
            }
        }
    }
}

// ---------------------------------------------------------------- boundary
__global__ void boundary_kernel(float* __restrict__ out) {
    const int PER = 2 * WP + 2 * HC;   // 772
    int tid = blockIdx.x * blockDim.x + threadIdx.x;
    int total = B_ * OG * PER;
    if (tid >= total) return;

    int p   = tid % PER;
    int bog = tid / PER;
    int og  = bog % OG;
    int b   = bog / OG;

    int y, xx;
    if (p < WP)               { y = 0;      xx = p; }
    else if (p < 2 * WP)      { y = HP - 1; xx = p - WP; }
    else if (p < 2 * WP + HC) { xx = 0;      y = p - 2 * WP + 1; }
    else                      { xx = WP - 1; y = p - (2 * WP + HC) + 1; }

    int sx = xx, dt = 0;
    if (xx == 0)           { sx = WP - 2; dt = 1; }
    else if (xx == WP - 1) { sx = 1;      dt = -1; }
    int sy = y;
    if (y == 0)            sy = HP - 2;
    else if (y == HP - 1)  sy = 1;

    int o = og / 12, t = og % 12;
    int f = t / 6,   rr = t % 6;
    int gp = f * 6 + ((rr + dt + 6) % 6);
    int og_src = o * 12 + gp;

    out[((size_t)(b * OG + og) * HP + y) * WP + xx] =
        out[((size_t)(b * OG + og_src) * HP + sy) * WP + sx];
}

// ---------------------------------------------------------------- launch
extern "C" void kernel_launch(void* const* d_in, const int* in_sizes, int n_in,
                              void* d_out, int out_size) {
    (void)in_sizes; (void)n_in; (void)out_size;
    const float* x    = (const float*)d_in[0];
    const float* w    = (const float*)d_in[1];
    const float* bias = (const float*)d_in[2];
    float* out = (float*)d_out;

    cudaFuncSetAttribute(conv_mma, cudaFuncAttributeMaxDynamicSharedMemorySize,
                         SMEM_TOT);

    prep_kernel<<<(OG * CG + 255) / 256, 256>>>(w);

    dim3 grid(WC / 64, HC, B_);   // (5, 64, 8) = 2560 CTAs
    conv_mma<<<grid, NTHR, SMEM_TOT>>>(x, bias, out);

    int total = B_ * OG * (2 * WP + 2 * HC);
    boundary_kernel<<<(total + 255) / 256, 256>>>(out);
}

// round 8
// speedup vs baseline: 1.8181x; 1.0584x over previous
#include <cuda_runtime.h>
#include <cuda_fp16.h>
#include <cstdint>

// ---------------------------------------------------------------- constants
#define B_   8
#define CG   192
#define OG   192
#define HP   66
#define WP   322
#define HC   64
#define WC   320
#define KTOT 1344            // CG * 7 hex taps
#define NCH  21              // KTOT / 64  (Kc = 64)
#define NTHR 256
#define NTILE 2560           // 5 x 64 x 8

// Weights (half) in mma-fragment layout:
// [chunk32x42][ks2][nb24][lane32][4 halves] (reg*2+half)
__device__ __half g_Kt[42 * 6144];
__device__ unsigned g_tile;

// tap -> offset (dy*WP + dx) for hex positions
__constant__ int c_off[7] = {WP + 1, 0, 1, WP + 2, 2 * WP + 2, 2 * WP + 1, WP};

// ---------------------------------------------------------------- utils
__device__ __forceinline__ uint32_t smem_u32(const void* p) {
    uint32_t a;
    asm("{ .reg .u64 t; cvta.to.shared.u64 t, %1; cvt.u32.u64 %0, t; }"
        : "=r"(a) : "l"(p));
    return a;
}

// ---------------------------------------------------------------- prep
// One thread per (og, cg, tap): expand w via p6m group tables into fragment
// layout. Also resets the persistent-tile counter.
__global__ void prep_kernel(const float* __restrict__ w) {
    if (blockIdx.x == 0 && threadIdx.x == 0) g_tile = 0;
    int idx = blockIdx.x * blockDim.x + threadIdx.x;
    if (idx >= OG * CG * 7) return;
    int t   = idx % 7;
    int rem = idx / 7;
    int cg  = rem % CG;
    int og  = rem / CG;
    int o = og / 12, g = og % 12;
    int c = cg / 12, h = cg % 12;
    int fg = g / 6, rg = g % 6;
    int fh = h / 6, rh = h % 6;
    int f = fg ^ fh;
    int r = (fg == 0) ? ((rh - rg + 6) % 6) : ((rg - rh + 6) % 6);
    int p = f * 6 + r;

    int tap;
    if (t == 0) tap = 0;
    else {
        int i = t - 1;
        int src = (fg == 0) ? ((i - rg + 12) % 6) : ((rg - i + 12) % 6);
        tap = 1 + src;
    }
    float val = w[(((o * 16 + c) * 12 + p) * 7) + tap];

    int nb = og >> 3;
    int n  = og & 7;
    int k    = cg * 7 + t;
    int ch   = k >> 5;
    int kk   = k & 31;
    int ks   = kk >> 4;
    int kk16 = kk & 15;
    int lane = n * 4 + ((kk16 & 7) >> 1);
    int reg  = kk16 >> 3;
    int half = kk16 & 1;
    g_Kt[(size_t)(((ch * 2 + ks) * 24 + nb) * 32 + lane) * 4 + reg * 2 + half] =
        __float2half_rn(val);
}

// ---------------------------------------------------------------- conv
// Persistent CTAs, dynamic tile queue. Tile = 64 px (1 row x 64 cols) x 192 og.
// 8 warps: 2M x 4N, warp tile 32x48. Kc = 64 (two 32-K subs), 21 iterations.
// SMEM: A 2 x 8KB at 0 ; B 2 x 24KB at 16384 ; bias at 65536 ; tile slot at 66304
#define SMEM_B_OFF 16384
#define SMEM_BIAS  65536
#define SMEM_TILE  66304
#define SMEM_TOT   (66304 + 16)

__global__ void __launch_bounds__(NTHR, 2) conv_mma(
    const float* __restrict__ x,
    const float* __restrict__ bias,
    float* __restrict__ out)
{
    extern __shared__ char smem[];
    const uint32_t sb = smem_u32(smem);
    const int tid  = threadIdx.x;
    const int lane = tid & 31;
    const int wrp  = tid >> 5;
    const int wm   = wrp >> 2;      // 0..1
    const int wn   = wrp & 3;       // 0..3

    if (tid < OG) ((float*)(smem + SMEM_BIAS))[tid] = bias[tid / 12];

    // ---- A producer constants (tile-independent) ----
    const int kpl  = (lane >> 4) + wrp * 2;     // 0..15 within a 32-K sub
    const int p_ks = kpl >> 3;
    const int l_c  = (kpl & 3) + (lane & 7) * 4;
    const int sreg = ((lane >> 3) & 1) + ((kpl >> 2) & 1) * 2;
    const uint32_t a_sts0 = sb + (uint32_t)(p_ks * 2048 + l_c * 16 + sreg * 4);
    const int mcol = lane & 15;

    const size_t plane = (size_t)HP * WP;
    volatile unsigned* s_tile = (volatile unsigned*)(smem + SMEM_TILE);

    uint32_t v[2][4];
    float acc[2][6][4];

#define LOAD_A_CHUNK(ch)                                                      \
    do {                                                                      \
        _Pragma("unroll")                                                     \
        for (int u = 0; u < 2; u++) {                                         \
            int k0 = (ch) * 64 + u * 32 + kpl * 2;                            \
            int k1 = k0 + 1;                                                  \
            const float* p0 = xb + (size_t)(k0 / 7) * plane + c_off[k0 % 7];  \
            const float* p1 = xb + (size_t)(k1 / 7) * plane + c_off[k1 % 7];  \
            _Pragma("unroll")                                                 \
            for (int e = 0; e < 4; e++) {                                     \
                float f0 = __ldg(p0 + e * 16);                                \
                float f1 = __ldg(p1 + e * 16);                                \
                __half2 hh = __halves2half2(__float2half_rn(f0),              \
                                            __float2half_rn(f1));             \
                v[u][e] = *(uint32_t*)&hh;                                    \
            }                                                                 \
        }                                                                     \
    } while (0)

#define STORE_A_CHUNK(stage)                                                  \
    do {                                                                      \
        uint32_t base = a_sts0 + (stage) * 8192;                              \
        _Pragma("unroll")                                                     \
        for (int u = 0; u < 2; u++)                                           \
            _Pragma("unroll")                                                 \
            for (int e = 0; e < 4; e++)                                       \
                asm volatile("st.shared.b32 [%0], %1;"                        \
                             :: "r"(base + u * 4096 + e * 512), "r"(v[u][e]));\
    } while (0)

#define LOAD_B_CHUNK(ch, stage)                                               \
    do {                                                                      \
        const __half* src = g_Kt + (size_t)(ch) * 12288 + tid * 8;            \
        uint32_t dst = sb + SMEM_B_OFF + (stage) * 24576 + tid * 16;          \
        _Pragma("unroll")                                                     \
        for (int i = 0; i < 6; i++)                                           \
            asm volatile("cp.async.cg.shared.global [%0], [%1], 16;"          \
                         :: "r"(dst + i * 4096), "l"(src + i * 2048) : "memory"); \
        asm volatile("cp.async.commit_group;" ::: "memory");                  \
    } while (0)

    // ================= persistent tile loop =================
    while (true) {
        if (tid == 0) *s_tile = atomicAdd(&g_tile, 1u);
        __syncthreads();
        unsigned t = *s_tile;
        if (t >= NTILE) break;

        const int bx  = t % 5;
        const int rem = t / 5;
        const int cy  = rem & 63;
        const int b   = rem >> 6;
        const int cx0 = bx * 64;

        const float* xb = x + (size_t)b * CG * plane + (size_t)cy * WP
                        + cx0 + mcol;

#pragma unroll
        for (int i = 0; i < 2; i++)
#pragma unroll
            for (int j = 0; j < 6; j++)
#pragma unroll
                for (int q = 0; q < 4; q++) acc[i][j][q] = 0.f;

        // ---- stage 0 fill ----
        LOAD_A_CHUNK(0);
        LOAD_B_CHUNK(0, 0);
        STORE_A_CHUNK(0);
        asm volatile("cp.async.wait_group 0;" ::: "memory");
        __syncthreads();

        // ---- main K loop (21 chunks of 64) ----
        for (int ch = 0; ch < NCH; ch++) {
            const int s = ch & 1;
            if (ch + 1 < NCH) {
                LOAD_A_CHUNK(ch + 1);
                LOAD_B_CHUNK(ch + 1, s ^ 1);
            }

            const uint32_t Ab = sb + s * 8192 + (uint32_t)(wm * 2 * 512 + lane * 16);
            const uint32_t Bb = sb + SMEM_B_OFF + s * 24576
                              + (uint32_t)((wn * 6) * 256 + lane * 8);
#pragma unroll
            for (int ks = 0; ks < 4; ks++) {
                uint32_t a[2][4];
#pragma unroll
                for (int mf = 0; mf < 2; mf++)
                    asm volatile("ld.shared.v4.b32 {%0,%1,%2,%3}, [%4];"
                        : "=r"(a[mf][0]), "=r"(a[mf][1]), "=r"(a[mf][2]), "=r"(a[mf][3])
                        : "r"(Ab + ks * 2048 + mf * 512));
                uint32_t bf[6][2];
#pragma unroll
                for (int nf = 0; nf < 6; nf++)
                    asm volatile("ld.shared.v2.b32 {%0,%1}, [%2];"
                        : "=r"(bf[nf][0]), "=r"(bf[nf][1])
                        : "r"(Bb + ks * 6144 + nf * 256));
#pragma unroll
                for (int mf = 0; mf < 2; mf++)
#pragma unroll
                    for (int nf = 0; nf < 6; nf++)
                        asm volatile(
                            "mma.sync.aligned.m16n8k16.row.col.f32.f16.f16.f32 "
                            "{%0,%1,%2,%3}, {%4,%5,%6,%7}, {%8,%9}, {%0,%1,%2,%3};"
                            : "+f"(acc[mf][nf][0]), "+f"(acc[mf][nf][1]),
                              "+f"(acc[mf][nf][2]), "+f"(acc[mf][nf][3])
                            : "r"(a[mf][0]), "r"(a[mf][1]), "r"(a[mf][2]), "r"(a[mf][3]),
                              "r"(bf[nf][0]), "r"(bf[nf][1]));
            }

            if (ch + 1 < NCH) STORE_A_CHUNK(s ^ 1);
            asm volatile("cp.async.wait_group 0;" ::: "memory");
            __syncthreads();
        }

        // ---- epilogue: bias + store interior (row cy+1) ----
        const float* bs = (const float*)(smem + SMEM_BIAS);
#pragma unroll
        for (int mf = 0; mf < 2; mf++) {
#pragma unroll
            for (int half = 0; half < 2; half++) {
                int m = wm * 32 + mf * 16 + (lane >> 2) + half * 8;   // 0..63
                float* orow = out + (size_t)b * OG * plane
                            + (size_t)(cy + 1) * WP + (cx0 + m + 1);
#pragma unroll
                for (int nf = 0; nf < 6; nf++) {
                    int og = wn * 48 + nf * 8 + (lane & 3) * 2;
                    orow[(size_t)og * plane]       = acc[mf][nf][half * 2 + 0] + bs[og];
                    orow[(size_t)(og + 1) * plane] = acc[mf][nf][half * 2 + 1] + bs[og + 1];
                }
            }
        }
        // epilogue uses registers only; next tile's smem writes are gated by
        // the tile-grab __syncthreads at loop top.
    }
}

// ---------------------------------------------------------------- boundary
__global__ void boundary_kernel(float* __restrict__ out) {
    const int PER = 2 * WP + 2 * HC;   // 772
    int tid = blockIdx.x * blockDim.x + threadIdx.x;
    int total = B_ * OG * PER;
    if (tid >= total) return;

    int p   = tid % PER;
    int bog = tid / PER;
    int og  = bog % OG;
    int b   = bog / OG;

    int y, xx;
    if (p < WP)               { y = 0;      xx = p; }
    else if (p < 2 * WP)      { y = HP - 1; xx = p - WP; }
    else if (p < 2 * WP + HC) { xx = 0;      y = p - 2 * WP + 1; }
    else                      { xx = WP - 1; y = p - (2 * WP + HC) + 1; }

    int sx = xx, dt = 0;
    if (xx == 0)           { sx = WP - 2; dt = 1; }
    else if (xx == WP - 1) { sx = 1;      dt = -1; }
    int sy = y;
    if (y == 0)            sy = HP - 2;
    else if (y == HP - 1)  sy = 1;

    int o = og / 12, t = og % 12;
    int f = t / 6,   rr = t % 6;
    int gp = f * 6 + ((rr + dt + 6) % 6);
    int og_src = o * 12 + gp;

    out[((size_t)(b * OG + og) * HP + y) * WP + xx] =
        out[((size_t)(b * OG + og_src) * HP + sy) * WP + sx];
}

// ---------------------------------------------------------------- launch
extern "C" void kernel_launch(void* const* d_in, const int* in_sizes, int n_in,
                              void* d_out, int out_size) {
    (void)in_sizes; (void)n_in; (void)out_size;
    const float* x    = (const float*)d_in[0];
    const float* w    = (const float*)d_in[1];
    const float* bias = (const float*)d_in[2];
    float* out = (float*)d_out;

    cudaFuncSetAttribute(conv_mma, cudaFuncAttributeMaxDynamicSharedMemorySize,
                         SMEM_TOT);

    prep_kernel<<<(OG * CG * 7 + 255) / 256, 256>>>(w);

    conv_mma<<<304, NTHR, SMEM_TOT>>>(x, bias, out);

    int total = B_ * OG * (2 * WP + 2 * HC);
    boundary_kernel<<<(total + 255) / 256, 256>>>(out);
}